// round 3
// baseline (speedup 1.0000x reference)
#include <cuda_runtime.h>
#include <math.h>

// Problem constants (fixed shapes)
#define NB   128           // batch
#define TT   512           // timesteps
#define DD   1024          // input dim
#define HH   1024          // hidden dim

// ---------------------------------------------------------------------------
// Phase 1: xw = x @ Wx + b   (M=NB*TT=65536, K=DD, N=HH), written into d_out
// Classic fp32 SGEMM: BM=128, BN=128, BK=8, 256 threads, 8x8 per-thread tile
// ---------------------------------------------------------------------------
#define BM 128
#define BN 128
#define BK 8

__global__ __launch_bounds__(256)
void sgemm_bias_kernel(const float* __restrict__ A,   // (M, K) = x flattened
                       const float* __restrict__ B,   // (K, N) = Wx
                       const float* __restrict__ bias,
                       float* __restrict__ C)         // (M, N) = out
{
    __shared__ float As[BK][BM];      // k-major, m contiguous
    __shared__ float Bs[BK][BN];

    const int bx = blockIdx.x;        // n tile: 0..7
    const int by = blockIdx.y;        // m tile: 0..511
    const int tid = threadIdx.x;
    const int tx = tid & 15;          // 0..15 (n)
    const int ty = tid >> 4;          // 0..15 (m)

    const int m_base = by * BM;
    const int n_base = bx * BN;

    // A-load mapping: each thread loads one float4 (128x8 tile = 1024 floats / 256 thr)
    const int ar = tid >> 1;          // 0..127 (row within tile)
    const int ac = (tid & 1) * 4;     // 0 or 4 (col within BK)
    // B-load mapping: 8x128 tile, one float4 per thread
    const int br = tid >> 5;          // 0..7
    const int bc = (tid & 31) * 4;    // 0..124

    float acc[8][8];
#pragma unroll
    for (int i = 0; i < 8; ++i)
#pragma unroll
        for (int j = 0; j < 8; ++j) acc[i][j] = 0.0f;

    const float* Arow = A + (size_t)(m_base + ar) * DD + ac;
    const float* Brow = B + (size_t)br * HH + n_base + bc;

    for (int k0 = 0; k0 < DD; k0 += BK) {
        // load A tile (transpose into k-major)
        float4 av = *(const float4*)(Arow + k0);
        As[ac + 0][ar] = av.x;
        As[ac + 1][ar] = av.y;
        As[ac + 2][ar] = av.z;
        As[ac + 3][ar] = av.w;
        // load B tile
        float4 bv = *(const float4*)(Brow + (size_t)k0 * HH);
        *(float4*)&Bs[br][bc] = bv;
        __syncthreads();

#pragma unroll
        for (int k = 0; k < BK; ++k) {
            float a[8], b[8];
            *(float4*)&a[0] = *(const float4*)&As[k][ty * 8];
            *(float4*)&a[4] = *(const float4*)&As[k][ty * 8 + 4];
            *(float4*)&b[0] = *(const float4*)&Bs[k][tx * 8];
            *(float4*)&b[4] = *(const float4*)&Bs[k][tx * 8 + 4];
#pragma unroll
            for (int i = 0; i < 8; ++i)
#pragma unroll
                for (int j = 0; j < 8; ++j)
                    acc[i][j] = fmaf(a[i], b[j], acc[i][j]);
        }
        __syncthreads();
    }

    // epilogue: add bias, store
    float bb[8];
    *(float4*)&bb[0] = *(const float4*)(bias + n_base + tx * 8);
    *(float4*)&bb[4] = *(const float4*)(bias + n_base + tx * 8 + 4);
#pragma unroll
    for (int i = 0; i < 8; ++i) {
        float* crow = C + (size_t)(m_base + ty * 8 + i) * HH + n_base + tx * 8;
        float4 v0, v1;
        v0.x = acc[i][0] + bb[0]; v0.y = acc[i][1] + bb[1];
        v0.z = acc[i][2] + bb[2]; v0.w = acc[i][3] + bb[3];
        v1.x = acc[i][4] + bb[4]; v1.y = acc[i][5] + bb[5];
        v1.z = acc[i][6] + bb[6]; v1.w = acc[i][7] + bb[7];
        *(float4*)(crow)     = v0;
        *(float4*)(crow + 4) = v1;
    }
}

// ---------------------------------------------------------------------------
// Phase 2: persistent recurrence kernel with software grid barrier.
//   for t in 0..TT-1:  out[:,t,:] = tanh(out[:,t,:] + h_prev @ Wh)
//   h_prev = h0 (t==0) else out[:,t-1,:]
// Grid = 128 CTAs (single wave on 148 SMs), 256 threads, 32x32 output tiles.
// ---------------------------------------------------------------------------
#define GRID2 128
#define BM2 32
#define BN2 32
#define BK2 32

__device__ unsigned g_gen   = 0;   // monotonically increasing generation
__device__ unsigned g_count = 0;   // self-resetting arrival counter

__device__ __forceinline__ void grid_barrier()
{
    __syncthreads();
    if (threadIdx.x == 0) {
        __threadfence();                       // release my writes
        volatile unsigned* genp = &g_gen;
        unsigned my_gen = *genp;               // read BEFORE arriving (safe: barrier
                                               // cannot complete without my arrival)
        unsigned old = atomicAdd(&g_count, 1u);
        if (old == GRID2 - 1) {
            atomicExch(&g_count, 0u);          // reset for next barrier
            __threadfence();
            atomicAdd(&g_gen, 1u);             // release everyone
        } else {
            while (*genp == my_gen) { }        // spin in L2
        }
        __threadfence();                       // acquire others' writes
    }
    __syncthreads();
}

__global__ __launch_bounds__(256)
void rnn_scan_kernel(const float* __restrict__ h0,
                     const float* __restrict__ Wh,   // (H, H) row-major
                     float* __restrict__ out)        // (NB, TT, HH)
{
    __shared__ float As[BK2][BM2 + 2];   // h_prev tile, k-major (pad keeps f2 align)
    __shared__ float Bs[BK2][BN2];       // Wh tile

    const int bid = blockIdx.x;
    const int bm = bid >> 5;      // 0..3   (m tile)
    const int bn = bid & 31;      // 0..31  (n tile)
    const int tid = threadIdx.x;
    const int tx = tid & 15;      // n dir
    const int ty = tid >> 4;      // m dir
    const int m0 = ty * 2;        // local m of this thread's 2x2 tile
    const int n0 = tx * 2;

    // load mapping for 32x32 tiles: thread -> (row = tid>>3, 4 cols at (tid&7)*4)
    const int lr = tid >> 3;          // 0..31
    const int lc = (tid & 7) * 4;     // 0..28

    for (int t = 0; t < TT; ++t) {
        const float* hprev;
        size_t hstride;
        if (t == 0) { hprev = h0;                      hstride = HH; }
        else        { hprev = out + (size_t)(t - 1) * HH; hstride = (size_t)TT * HH; }

        float acc00 = 0.f, acc01 = 0.f, acc10 = 0.f, acc11 = 0.f;

        for (int k0 = 0; k0 < HH; k0 += BK2) {
            // A tile: rows (bm*32 + lr) of h_prev, cols k0+lc..+3 ; store transposed
            {
                float4 v = *(const float4*)(hprev + (size_t)(bm * BM2 + lr) * hstride
                                            + k0 + lc);
                As[lc + 0][lr] = v.x;
                As[lc + 1][lr] = v.y;
                As[lc + 2][lr] = v.z;
                As[lc + 3][lr] = v.w;
            }
            // B tile: Wh rows k0+lr, cols bn*32 + lc..+3
            {
                float4 v = *(const float4*)(Wh + (size_t)(k0 + lr) * HH
                                            + bn * BN2 + lc);
                *(float4*)&Bs[lr][lc] = v;
            }
            __syncthreads();

#pragma unroll
            for (int k = 0; k < BK2; ++k) {
                float2 a = *(const float2*)&As[k][m0];
                float2 b = *(const float2*)&Bs[k][n0];
                acc00 = fmaf(a.x, b.x, acc00);
                acc01 = fmaf(a.x, b.y, acc01);
                acc10 = fmaf(a.y, b.x, acc10);
                acc11 = fmaf(a.y, b.y, acc11);
            }
            __syncthreads();
        }

        // epilogue: h_t = tanh(xw_t + acc), in place in out[:, t, :]
        {
            const int gm0 = bm * BM2 + m0;           // global batch rows
            const int gn0 = bn * BN2 + n0;           // global hidden cols
            float* p0 = out + (size_t)gm0 * TT * HH + (size_t)t * HH + gn0;
            float* p1 = p0 + (size_t)TT * HH;        // row gm0+1
            float2 x0 = *(const float2*)p0;
            float2 x1 = *(const float2*)p1;
            x0.x = tanhf(x0.x + acc00);
            x0.y = tanhf(x0.y + acc01);
            x1.x = tanhf(x1.x + acc10);
            x1.y = tanhf(x1.y + acc11);
            *(float2*)p0 = x0;
            *(float2*)p1 = x1;
        }

        grid_barrier();   // all h_t visible before anyone reads it at t+1
    }
}

// ---------------------------------------------------------------------------
// Launch
// ---------------------------------------------------------------------------
extern "C" void kernel_launch(void* const* d_in, const int* in_sizes, int n_in,
                              void* d_out, int out_size)
{
    const float* x  = (const float*)d_in[0];   // (N, T, D)
    const float* h0 = (const float*)d_in[1];   // (N, H)
    const float* Wx = (const float*)d_in[2];   // (D, H)
    const float* Wh = (const float*)d_in[3];   // (H, H)
    const float* b  = (const float*)d_in[4];   // (H,)
    float* out = (float*)d_out;                // (N, T, H)

    // Phase 1: xw -> out
    dim3 g1(HH / BN, (NB * TT) / BM);          // (8, 512)
    sgemm_bias_kernel<<<g1, 256>>>(x, Wx, b, out);

    // Phase 2: sequential scan, persistent kernel
    rnn_scan_kernel<<<GRID2, 256>>>(h0, Wh, out);
}

// round 4
// speedup vs baseline: 1.1152x; 1.1152x over previous
#include <cuda_runtime.h>
#include <math.h>

// Problem constants (fixed shapes)
#define NB   128           // batch
#define TT   512           // timesteps
#define DD   1024          // input dim
#define HH   1024          // hidden dim

// ---------------------------------------------------------------------------
// Phase 1: xw = x @ Wx + b   (M=NB*TT=65536, K=DD, N=HH), written into d_out
// Classic fp32 SGEMM: BM=128, BN=128, BK=8, 256 threads, 8x8 per-thread tile
// ---------------------------------------------------------------------------
#define BM 128
#define BN 128
#define BK 8

__global__ __launch_bounds__(256)
void sgemm_bias_kernel(const float* __restrict__ A,   // (M, K) = x flattened
                       const float* __restrict__ B,   // (K, N) = Wx
                       const float* __restrict__ bias,
                       float* __restrict__ C)         // (M, N) = out
{
    __shared__ float As[BK][BM];      // k-major, m contiguous
    __shared__ float Bs[BK][BN];

    const int bx = blockIdx.x;        // n tile: 0..7
    const int by = blockIdx.y;        // m tile: 0..511
    const int tid = threadIdx.x;
    const int tx = tid & 15;          // 0..15 (n)
    const int ty = tid >> 4;          // 0..15 (m)

    const int m_base = by * BM;
    const int n_base = bx * BN;

    // A-load mapping: each thread loads one float4 (128x8 tile = 1024 floats / 256 thr)
    const int ar = tid >> 1;          // 0..127 (row within tile)
    const int ac = (tid & 1) * 4;     // 0 or 4 (col within BK)
    // B-load mapping: 8x128 tile, one float4 per thread
    const int br = tid >> 5;          // 0..7
    const int bc = (tid & 31) * 4;    // 0..124

    float acc[8][8];
#pragma unroll
    for (int i = 0; i < 8; ++i)
#pragma unroll
        for (int j = 0; j < 8; ++j) acc[i][j] = 0.0f;

    const float* Arow = A + (size_t)(m_base + ar) * DD + ac;
    const float* Brow = B + (size_t)br * HH + n_base + bc;

    for (int k0 = 0; k0 < DD; k0 += BK) {
        // load A tile (transpose into k-major)
        float4 av = *(const float4*)(Arow + k0);
        As[ac + 0][ar] = av.x;
        As[ac + 1][ar] = av.y;
        As[ac + 2][ar] = av.z;
        As[ac + 3][ar] = av.w;
        // load B tile
        float4 bv = *(const float4*)(Brow + (size_t)k0 * HH);
        *(float4*)&Bs[br][bc] = bv;
        __syncthreads();

#pragma unroll
        for (int k = 0; k < BK; ++k) {
            float a[8], b[8];
            *(float4*)&a[0] = *(const float4*)&As[k][ty * 8];
            *(float4*)&a[4] = *(const float4*)&As[k][ty * 8 + 4];
            *(float4*)&b[0] = *(const float4*)&Bs[k][tx * 8];
            *(float4*)&b[4] = *(const float4*)&Bs[k][tx * 8 + 4];
#pragma unroll
            for (int i = 0; i < 8; ++i)
#pragma unroll
                for (int j = 0; j < 8; ++j)
                    acc[i][j] = fmaf(a[i], b[j], acc[i][j]);
        }
        __syncthreads();
    }

    // epilogue: add bias, store
    float bb[8];
    *(float4*)&bb[0] = *(const float4*)(bias + n_base + tx * 8);
    *(float4*)&bb[4] = *(const float4*)(bias + n_base + tx * 8 + 4);
#pragma unroll
    for (int i = 0; i < 8; ++i) {
        float* crow = C + (size_t)(m_base + ty * 8 + i) * HH + n_base + tx * 8;
        float4 v0, v1;
        v0.x = acc[i][0] + bb[0]; v0.y = acc[i][1] + bb[1];
        v0.z = acc[i][2] + bb[2]; v0.w = acc[i][3] + bb[3];
        v1.x = acc[i][4] + bb[4]; v1.y = acc[i][5] + bb[5];
        v1.z = acc[i][6] + bb[6]; v1.w = acc[i][7] + bb[7];
        *(float4*)(crow)     = v0;
        *(float4*)(crow + 4) = v1;
    }
}

// ---------------------------------------------------------------------------
// Phase 2: persistent recurrence kernel with software grid barrier.
//   for t in 0..TT-1:  out[:,t,:] = tanh(out[:,t,:] + h_prev @ Wh)
//   h_prev = h0 (t==0) else out[:,t-1,:]
// Grid = 128 CTAs (single wave on 148 SMs), 256 threads, 32x32 output tiles.
// ---------------------------------------------------------------------------
#define GRID2 128
#define BM2 32
#define BN2 32
#define BK2 32

__device__ unsigned g_gen   = 0;   // monotonically increasing generation
__device__ unsigned g_count = 0;   // self-resetting arrival counter

__device__ __forceinline__ void grid_barrier()
{
    __syncthreads();
    if (threadIdx.x == 0) {
        __threadfence();                       // release my writes
        volatile unsigned* genp = &g_gen;
        unsigned my_gen = *genp;               // read BEFORE arriving (safe: barrier
                                               // cannot complete without my arrival)
        unsigned old = atomicAdd(&g_count, 1u);
        if (old == GRID2 - 1) {
            atomicExch(&g_count, 0u);          // reset for next barrier
            __threadfence();
            atomicAdd(&g_gen, 1u);             // release everyone
        } else {
            while (*genp == my_gen) { }        // spin in L2
        }
        __threadfence();                       // acquire others' writes
    }
    __syncthreads();
}

__global__ __launch_bounds__(256)
void rnn_scan_kernel(const float* __restrict__ h0,
                     const float* __restrict__ Wh,   // (H, H) row-major
                     float* __restrict__ out)        // (NB, TT, HH)
{
    __shared__ float As[BK2][BM2 + 2];   // h_prev tile, k-major (pad keeps f2 align)
    __shared__ float Bs[BK2][BN2];       // Wh tile

    const int bid = blockIdx.x;
    const int bm = bid >> 5;      // 0..3   (m tile)
    const int bn = bid & 31;      // 0..31  (n tile)
    const int tid = threadIdx.x;
    const int tx = tid & 15;      // n dir
    const int ty = tid >> 4;      // m dir
    const int m0 = ty * 2;        // local m of this thread's 2x2 tile
    const int n0 = tx * 2;

    // load mapping for 32x32 tiles: thread -> (row = tid>>3, 4 cols at (tid&7)*4)
    const int lr = tid >> 3;          // 0..31
    const int lc = (tid & 7) * 4;     // 0..28

    for (int t = 0; t < TT; ++t) {
        const float* hprev;
        size_t hstride;
        if (t == 0) { hprev = h0;                      hstride = HH; }
        else        { hprev = out + (size_t)(t - 1) * HH; hstride = (size_t)TT * HH; }

        float acc00 = 0.f, acc01 = 0.f, acc10 = 0.f, acc11 = 0.f;

        for (int k0 = 0; k0 < HH; k0 += BK2) {
            // A tile: rows (bm*32 + lr) of h_prev, cols k0+lc..+3 ; store transposed
            {
                float4 v = *(const float4*)(hprev + (size_t)(bm * BM2 + lr) * hstride
                                            + k0 + lc);
                As[lc + 0][lr] = v.x;
                As[lc + 1][lr] = v.y;
                As[lc + 2][lr] = v.z;
                As[lc + 3][lr] = v.w;
            }
            // B tile: Wh rows k0+lr, cols bn*32 + lc..+3
            {
                float4 v = *(const float4*)(Wh + (size_t)(k0 + lr) * HH
                                            + bn * BN2 + lc);
                *(float4*)&Bs[lr][lc] = v;
            }
            __syncthreads();

#pragma unroll
            for (int k = 0; k < BK2; ++k) {
                float2 a = *(const float2*)&As[k][m0];
                float2 b = *(const float2*)&Bs[k][n0];
                acc00 = fmaf(a.x, b.x, acc00);
                acc01 = fmaf(a.x, b.y, acc01);
                acc10 = fmaf(a.y, b.x, acc10);
                acc11 = fmaf(a.y, b.y, acc11);
            }
            __syncthreads();
        }

        // epilogue: h_t = tanh(xw_t + acc), in place in out[:, t, :]
        {
            const int gm0 = bm * BM2 + m0;           // global batch rows
            const int gn0 = bn * BN2 + n0;           // global hidden cols
            float* p0 = out + (size_t)gm0 * TT * HH + (size_t)t * HH + gn0;
            float* p1 = p0 + (size_t)TT * HH;        // row gm0+1
            float2 x0 = *(const float2*)p0;
            float2 x1 = *(const float2*)p1;
            x0.x = tanhf(x0.x + acc00);
            x0.y = tanhf(x0.y + acc01);
            x1.x = tanhf(x1.x + acc10);
            x1.y = tanhf(x1.y + acc11);
            *(float2*)p0 = x0;
            *(float2*)p1 = x1;
        }

        grid_barrier();   // all h_t visible before anyone reads it at t+1
    }
}

// ---------------------------------------------------------------------------
// Launch
// ---------------------------------------------------------------------------
extern "C" void kernel_launch(void* const* d_in, const int* in_sizes, int n_in,
                              void* d_out, int out_size)
{
    const float* x  = (const float*)d_in[0];   // (N, T, D)
    const float* h0 = (const float*)d_in[1];   // (N, H)
    const float* Wx = (const float*)d_in[2];   // (D, H)
    const float* Wh = (const float*)d_in[3];   // (H, H)
    const float* b  = (const float*)d_in[4];   // (H,)
    float* out = (float*)d_out;                // (N, T, H)

    // Phase 1: xw -> out
    dim3 g1(HH / BN, (NB * TT) / BM);          // (8, 512)
    sgemm_bias_kernel<<<g1, 256>>>(x, Wx, b, out);

    // Phase 2: sequential scan, persistent kernel
    rnn_scan_kernel<<<GRID2, 256>>>(h0, Wh, out);
}

// round 7
// speedup vs baseline: 1.2155x; 1.0899x over previous
#include <cuda_runtime.h>
#include <cuda_bf16.h>
#include <math.h>
#include <stdint.h>

#define NB 128
#define TT 512
#define DD 1024
#define HH 1024

// ---------------- helpers (arch-agnostic PTX only: sm_80+ features) ----------
__device__ __forceinline__ uint32_t smem_u32(const void* p) {
    uint32_t a;
    asm("{ .reg .u64 t; cvta.to.shared.u64 t, %1; cvt.u32.u64 %0, t; }"
        : "=r"(a) : "l"(p));
    return a;
}
__device__ __forceinline__ uint32_t swz(uint32_t b) { return b ^ ((b >> 3) & 0x70); }

__device__ __forceinline__ void ldm_x4(uint32_t* r, uint32_t a) {
    asm volatile("ldmatrix.sync.aligned.m8n8.x4.shared.b16 {%0,%1,%2,%3}, [%4];"
        : "=r"(r[0]), "=r"(r[1]), "=r"(r[2]), "=r"(r[3]) : "r"(a));
}
// D = A(bf16,row) * B(bf16,col) + D, m16n8k16, fp32 accum
__device__ __forceinline__ void mma_bf16(float* c, const uint32_t* a, const uint32_t* b) {
    asm volatile("mma.sync.aligned.m16n8k16.row.col.f32.bf16.bf16.f32 "
        "{%0,%1,%2,%3}, {%4,%5,%6,%7}, {%8,%9}, {%0,%1,%2,%3};"
        : "+f"(c[0]), "+f"(c[1]), "+f"(c[2]), "+f"(c[3])
        : "r"(a[0]), "r"(a[1]), "r"(a[2]), "r"(a[3]), "r"(b[0]), "r"(b[1]));
}
#define CP16(dst, src) \
    asm volatile("cp.async.cg.shared.global [%0], [%1], 16;" :: "r"(dst), "l"(src))
#define CP_COMMIT()   asm volatile("cp.async.commit_group;" ::: "memory")
#define CP_WAIT_ALL() asm volatile("cp.async.wait_group 0;" ::: "memory")

__device__ __forceinline__ void split2(float f0, float f1, uint32_t& hi, uint32_t& lo) {
    __nv_bfloat16 h0 = __float2bfloat16(f0);
    __nv_bfloat16 h1 = __float2bfloat16(f1);
    __nv_bfloat16 l0 = __float2bfloat16(f0 - __bfloat162float(h0));
    __nv_bfloat16 l1 = __float2bfloat16(f1 - __bfloat162float(h1));
    hi = (uint32_t)__bfloat16_as_ushort(h0) | ((uint32_t)__bfloat16_as_ushort(h1) << 16);
    lo = (uint32_t)__bfloat16_as_ushort(l0) | ((uint32_t)__bfloat16_as_ushort(l1) << 16);
}

// ---------------- global scratch (no allocation allowed) ----------------
__device__ __nv_bfloat16 g_WxT_hi[HH * DD];     // [n][k] = hi(Wx[k][n])
__device__ __nv_bfloat16 g_WxT_lo[HH * DD];
__device__ __nv_bfloat16 g_WhT_hi[HH * HH];     // [n][k] = hi(Wh[k][n])
__device__ __nv_bfloat16 g_WhT_lo[HH * HH];
__device__ __nv_bfloat16 g_h_hi[2][NB * HH];    // ping-pong split hidden state
__device__ __nv_bfloat16 g_h_lo[2][NB * HH];

__device__ unsigned g_gen   = 0;
__device__ unsigned g_count = 0;

// ---------------- prep ----------------
__global__ void split_transpose_kernel(const float* __restrict__ W, int which) {
    __nv_bfloat16* hi = which ? g_WhT_hi : g_WxT_hi;
    __nv_bfloat16* lo = which ? g_WhT_lo : g_WxT_lo;
    __shared__ float tile[32][33];
    const int kb = blockIdx.x * 32, nb = blockIdx.y * 32;
    const int tx = threadIdx.x, ty = threadIdx.y;    // (32, 8)
#pragma unroll
    for (int i = 0; i < 4; ++i)
        tile[ty + 8 * i][tx] = W[(size_t)(kb + ty + 8 * i) * HH + nb + tx];
    __syncthreads();
#pragma unroll
    for (int i = 0; i < 4; ++i) {
        float f = tile[tx][ty + 8 * i];              // W[kb+tx][nb+ty+8i]
        int n = nb + ty + 8 * i, k = kb + tx;
        __nv_bfloat16 h = __float2bfloat16(f);
        hi[(size_t)n * 1024 + k] = h;
        lo[(size_t)n * 1024 + k] = __float2bfloat16(f - __bfloat162float(h));
    }
}

__global__ void split_h0_kernel(const float* __restrict__ h0) {
    int i = blockIdx.x * blockDim.x + threadIdx.x;
    if (i < NB * HH) {
        float f = h0[i];
        __nv_bfloat16 h = __float2bfloat16(f);
        g_h_hi[1][i] = h;                            // step 0 reads parity 1
        g_h_lo[1][i] = __float2bfloat16(f - __bfloat162float(h));
    }
}

// =====================================================================
// Phase 1: out = x @ Wx + b.  CTA 128x128, 256 thr, 8 warps (2m x 4n),
// warp tile m64 x n32, k-chunks of 64, split-bf16 3-product mma.sync.
// SMEM/buffer: AH 16K | AL 16K | BH 16K | BL 16K = 64KB, occupancy 2.
// =====================================================================
#define P1_SMEM (65536 + 1024)

__global__ __launch_bounds__(256, 2)
void xw_gemm_kernel(const float* __restrict__ x, const float* __restrict__ bias,
                    float* __restrict__ out) {
    extern __shared__ char smem_raw[];
    char* smem = (char*)(((uintptr_t)smem_raw + 1023) & ~(uintptr_t)1023);
    const uint32_t sb = smem_u32(smem);
    const uint32_t AH = sb, AL = sb + 16384, BH = sb + 32768, BL = sb + 49152;

    const int tid = threadIdx.x, lane = tid & 31, w = tid >> 5;
    const int n1 = blockIdx.x * 128, m0 = blockIdx.y * 128;
    const int mq = w & 1, nq = w >> 1;               // warp: rows mq*64, cols nq*32

    const int li = lane >> 3, lr = lane & 7;
    const int aRow = mq * 64 + (li & 1) * 8 + lr;    // + mt*16
    const int aKof = (li >> 1) * 16;                 // bytes
    const int bRow = nq * 32 + (li >> 1) * 8 + lr;   // + g*16
    const int bKof = (li & 1) * 16;

    // staging map: row = tid>>1 (0..127), half = tid&1 (32 elems each)
    const int srow = tid >> 1, shalf = tid & 1;
    const uint32_t sbyte = (uint32_t)srow * 128 + shalf * 64;

    float C[4][4][4];
#pragma unroll
    for (int i = 0; i < 4; ++i)
#pragma unroll
        for (int j = 0; j < 4; ++j)
#pragma unroll
            for (int q = 0; q < 4; ++q) C[i][j][q] = 0.0f;

    for (int c = 0; c < 16; ++c) {
        const int k0 = c * 64;
        // stage A: x fp32 -> split bf16 hi/lo, swizzled
        {
            const float4* src = (const float4*)(x + (size_t)(m0 + srow) * DD + k0 + shalf * 32);
            float4 f4[8];
#pragma unroll
            for (int j = 0; j < 8; ++j) f4[j] = src[j];
            const float* ff = (const float*)f4;
            uint32_t hw[16], lw[16];
#pragma unroll
            for (int j = 0; j < 16; ++j) split2(ff[2 * j], ff[2 * j + 1], hw[j], lw[j]);
#pragma unroll
            for (int j = 0; j < 4; ++j) {
                const uint32_t bo = swz(sbyte + j * 16);
                *(uint4*)(smem + (AH - sb) + bo) = ((uint4*)hw)[j];
                *(uint4*)(smem + (AL - sb) + bo) = ((uint4*)lw)[j];
            }
        }
        // stage B: WxT hi/lo copy, swizzled
        {
            const uint4* sh = (const uint4*)(g_WxT_hi + (size_t)(n1 + srow) * DD + k0 + shalf * 32);
            const uint4* sl = (const uint4*)(g_WxT_lo + (size_t)(n1 + srow) * DD + k0 + shalf * 32);
#pragma unroll
            for (int j = 0; j < 4; ++j) {
                const uint32_t bo = swz(sbyte + j * 16);
                *(uint4*)(smem + (BH - sb) + bo) = sh[j];
                *(uint4*)(smem + (BL - sb) + bo) = sl[j];
            }
        }
        __syncthreads();

#pragma unroll
        for (int kk = 0; kk < 64; kk += 16) {
            uint32_t Bh[2][4], Bl[2][4];             // [g] covers n g*16..+15
#pragma unroll
            for (int g = 0; g < 2; ++g) {
                const uint32_t bo = swz((uint32_t)(bRow + g * 16) * 128 + kk * 2 + bKof);
                ldm_x4(Bh[g], BH + bo);
                ldm_x4(Bl[g], BL + bo);
            }
#pragma unroll
            for (int mt = 0; mt < 4; ++mt) {
                uint32_t Ahf[4], Alf[4];
                const uint32_t ao = swz((uint32_t)(aRow + mt * 16) * 128 + kk * 2 + aKof);
                ldm_x4(Ahf, AH + ao);
                ldm_x4(Alf, AL + ao);
#pragma unroll
                for (int nt = 0; nt < 4; ++nt) {
                    const uint32_t* bh = &Bh[nt >> 1][(nt & 1) * 2];
                    const uint32_t* bl = &Bl[nt >> 1][(nt & 1) * 2];
                    mma_bf16(C[mt][nt], Ahf, bh);
                    mma_bf16(C[mt][nt], Ahf, bl);
                    mma_bf16(C[mt][nt], Alf, bh);
                }
            }
        }
        __syncthreads();
    }

    // epilogue: + bias, store fp32
#pragma unroll
    for (int mt = 0; mt < 4; ++mt) {
#pragma unroll
        for (int nt = 0; nt < 4; ++nt) {
            const int r  = m0 + mq * 64 + mt * 16 + (lane >> 2);
            const int cc = n1 + nq * 32 + nt * 8 + (lane & 3) * 2;
            const float b0 = bias[cc], b1 = bias[cc + 1];
            float2 v0 = { C[mt][nt][0] + b0, C[mt][nt][1] + b1 };
            float2 v1 = { C[mt][nt][2] + b0, C[mt][nt][3] + b1 };
            *(float2*)(out + (size_t)r * HH + cc)       = v0;
            *(float2*)(out + (size_t)(r + 8) * HH + cc) = v1;
        }
    }
}

// =====================================================================
// Phase 2: persistent scan. 64 CTAs, 128 thr (4 warps m32 each), CTA
// N-slice = 16 cols. WhT slice resident in SMEM (64KB). h streamed as
// split bf16 from ping-pong global scratch via double-buffered cp.async.
// SMEM: Abuf0 (hi16K lo16K) | Abuf1 | BH 32K | BL 32K = 128KB.
// =====================================================================
#define GRID2 64
#define SC_SMEM (131072 + 1024)

__device__ __forceinline__ void grid_barrier() {
    __syncthreads();
    if (threadIdx.x == 0) {
        __threadfence();
        volatile unsigned* genp = &g_gen;
        unsigned my_gen = *genp;
        unsigned old = atomicAdd(&g_count, 1u);
        if (old == GRID2 - 1) {
            atomicExch(&g_count, 0u);
            __threadfence();
            atomicAdd(&g_gen, 1u);
        } else {
            while (*genp == my_gen) { }
        }
        __threadfence();
    }
    __syncthreads();
}

__device__ __forceinline__ void scan_issue_chunk(
        uint32_t dst_h, uint32_t dst_l,
        const __nv_bfloat16* __restrict__ rh, const __nv_bfloat16* __restrict__ rl,
        int c, int tid) {
    const char* sh = (const char*)(rh + (size_t)tid * HH + c * 64);
    const char* sl = (const char*)(rl + (size_t)tid * HH + c * 64);
    const uint32_t rowoff = (uint32_t)tid * 128;
#pragma unroll
    for (int u = 0; u < 8; ++u) CP16(dst_h + swz(rowoff + u * 16), sh + u * 16);
#pragma unroll
    for (int u = 0; u < 8; ++u) CP16(dst_l + swz(rowoff + u * 16), sl + u * 16);
}

__global__ __launch_bounds__(128, 1)
void rnn_scan_kernel(float* __restrict__ out) {
    extern __shared__ char smem_raw[];
    char* smem = (char*)(((uintptr_t)smem_raw + 1023) & ~(uintptr_t)1023);
    const uint32_t sb = smem_u32(smem);
    const int tid = threadIdx.x, lane = tid & 31, w = tid >> 5;
    const int n0 = blockIdx.x * 16;

    const uint32_t BH = sb + 65536, BL = sb + 98304;  // 16 chunks x 2KB each

    // stage resident B = WhT[n0..n0+15][all k], chunk-blocked swizzled
    {
        const int r = tid >> 3, u = tid & 7;          // row 0..15, 16B unit 0..7
        const uint32_t bo = swz((uint32_t)r * 128 + u * 16);
        for (int c = 0; c < 16; ++c) {
            const uint4 qh = *(const uint4*)(g_WhT_hi + (size_t)(n0 + r) * HH + c * 64 + u * 8);
            const uint4 ql = *(const uint4*)(g_WhT_lo + (size_t)(n0 + r) * HH + c * 64 + u * 8);
            *(uint4*)(smem + 65536 + c * 2048 + bo) = qh;
            *(uint4*)(smem + 98304 + c * 2048 + bo) = ql;
        }
    }
    __syncthreads();

    const int li = lane >> 3, lr = lane & 7;
    const int aRow = w * 32 + (li & 1) * 8 + lr;      // + mt*16
    const int aKof = (li >> 1) * 16;
    const int bRow = (li >> 1) * 8 + lr;
    const int bKof = (li & 1) * 16;

    // epilogue mapping
    const int r0 = w * 32 + (lane >> 2);              // + mt*16 (+8)
    const int cb = n0 + (lane & 3) * 2;               // + nt*8 (+1)

    // prologue: chunk 0 of step 0 (reads parity 1)
    scan_issue_chunk(sb, sb + 16384, g_h_hi[1], g_h_lo[1], 0, tid);
    CP_COMMIT();

    for (int t = 0; t < TT; ++t) {
        const __nv_bfloat16* rh = g_h_hi[(t & 1) ^ 1];
        const __nv_bfloat16* rl = g_h_lo[(t & 1) ^ 1];
        __nv_bfloat16* wh = g_h_hi[t & 1];
        __nv_bfloat16* wl = g_h_lo[t & 1];

        // prefetch xw slice for epilogue
        float2 xp[2][2][2];
#pragma unroll
        for (int mt = 0; mt < 2; ++mt)
#pragma unroll
            for (int nt = 0; nt < 2; ++nt) {
                const float* p = out + ((size_t)(r0 + mt * 16) * TT + t) * HH + cb + nt * 8;
                xp[mt][nt][0] = *(const float2*)p;
                xp[mt][nt][1] = *(const float2*)(p + (size_t)8 * TT * HH);
            }

        float C[2][2][4];
#pragma unroll
        for (int i = 0; i < 2; ++i)
#pragma unroll
            for (int j = 0; j < 2; ++j)
#pragma unroll
                for (int q = 0; q < 4; ++q) C[i][j][q] = 0.0f;

        for (int c = 0; c < 16; ++c) {
            CP_WAIT_ALL();
            __syncthreads();
            if (c < 15) {
                const uint32_t db = sb + ((c + 1) & 1) * 32768;
                scan_issue_chunk(db, db + 16384, rh, rl, c + 1, tid);
                CP_COMMIT();
            }
            const uint32_t bh_base = BH - 32768 * 0 + 0;  // (kept simple below)
            const uint32_t abase_h = sb + (c & 1) * 32768;
            const uint32_t abase_l = abase_h + 16384;
#pragma unroll
            for (int kk = 0; kk < 64; kk += 16) {
                uint32_t Bhf[4], Blf[4];
                const uint32_t bo = (uint32_t)c * 2048 + swz((uint32_t)bRow * 128 + kk * 2 + bKof);
                ldm_x4(Bhf, BH + bo);
                ldm_x4(Blf, BL + bo);
#pragma unroll
                for (int mt = 0; mt < 2; ++mt) {
                    uint32_t Ahf[4], Alf[4];
                    const uint32_t ao = swz((uint32_t)(aRow + mt * 16) * 128 + kk * 2 + aKof);
                    ldm_x4(Ahf, abase_h + ao);
                    ldm_x4(Alf, abase_l + ao);
#pragma unroll
                    for (int nt = 0; nt < 2; ++nt) {
                        const uint32_t* bh = &Bhf[nt * 2];
                        const uint32_t* bl = &Blf[nt * 2];
                        mma_bf16(C[mt][nt], Ahf, bh);
                        mma_bf16(C[mt][nt], Ahf, bl);
                        mma_bf16(C[mt][nt], Alf, bh);
                    }
                }
            }
        }

        // epilogue: h = tanh(xw + acc); write out fp32 + split h scratch
#pragma unroll
        for (int mt = 0; mt < 2; ++mt)
#pragma unroll
            for (int nt = 0; nt < 2; ++nt) {
                const int r  = r0 + mt * 16;
                const int cc = cb + nt * 8;
                float h00 = tanhf(xp[mt][nt][0].x + C[mt][nt][0]);
                float h01 = tanhf(xp[mt][nt][0].y + C[mt][nt][1]);
                float h10 = tanhf(xp[mt][nt][1].x + C[mt][nt][2]);
                float h11 = tanhf(xp[mt][nt][1].y + C[mt][nt][3]);
                float* p = out + ((size_t)r * TT + t) * HH + cc;
                float2 v0 = { h00, h01 }, v1 = { h10, h11 };
                *(float2*)p = v0;
                *(float2*)(p + (size_t)8 * TT * HH) = v1;
                uint32_t hi, lo;
                split2(h00, h01, hi, lo);
                *(uint32_t*)(wh + (size_t)r * HH + cc) = hi;
                *(uint32_t*)(wl + (size_t)r * HH + cc) = lo;
                split2(h10, h11, hi, lo);
                *(uint32_t*)(wh + (size_t)(r + 8) * HH + cc) = hi;
                *(uint32_t*)(wl + (size_t)(r + 8) * HH + cc) = lo;
            }

        grid_barrier();   // h_t globally visible (cp.async.cg reads bypass L1)

        if (t < TT - 1) {
            scan_issue_chunk(sb, sb + 16384, g_h_hi[t & 1], g_h_lo[t & 1], 0, tid);
            CP_COMMIT();
        }
    }
}

// ---------------- launch ----------------
extern "C" void kernel_launch(void* const* d_in, const int* in_sizes, int n_in,
                              void* d_out, int out_size)
{
    const float* x  = (const float*)d_in[0];
    const float* h0 = (const float*)d_in[1];
    const float* Wx = (const float*)d_in[2];
    const float* Wh = (const float*)d_in[3];
    const float* b  = (const float*)d_in[4];
    float* out = (float*)d_out;

    cudaFuncSetAttribute(xw_gemm_kernel,
        cudaFuncAttributeMaxDynamicSharedMemorySize, P1_SMEM);
    cudaFuncSetAttribute(rnn_scan_kernel,
        cudaFuncAttributeMaxDynamicSharedMemorySize, SC_SMEM);

    dim3 tb(32, 8);
    split_transpose_kernel<<<dim3(32, 32), tb>>>(Wx, 0);
    split_transpose_kernel<<<dim3(32, 32), tb>>>(Wh, 1);
    split_h0_kernel<<<(NB * HH + 255) / 256, 256>>>(h0);

    xw_gemm_kernel<<<dim3(8, 512), 256, P1_SMEM>>>(x, b, out);
    rnn_scan_kernel<<<GRID2, 128, SC_SMEM>>>(out);
}

// round 8
// speedup vs baseline: 2.3885x; 1.9650x over previous
#include <cuda_runtime.h>
#include <cuda_bf16.h>
#include <math.h>
#include <stdint.h>

#define NB 128
#define TT 512
#define DD 1024
#define HH 1024

// ---------------- helpers (arch-agnostic PTX only: sm_80+ features) ----------
__device__ __forceinline__ uint32_t smem_u32(const void* p) {
    uint32_t a;
    asm("{ .reg .u64 t; cvta.to.shared.u64 t, %1; cvt.u32.u64 %0, t; }"
        : "=r"(a) : "l"(p));
    return a;
}
__device__ __forceinline__ uint32_t swz(uint32_t b) { return b ^ ((b >> 3) & 0x70); }

__device__ __forceinline__ void ldm_x4(uint32_t* r, uint32_t a) {
    asm volatile("ldmatrix.sync.aligned.m8n8.x4.shared.b16 {%0,%1,%2,%3}, [%4];"
        : "=r"(r[0]), "=r"(r[1]), "=r"(r[2]), "=r"(r[3]) : "r"(a));
}
__device__ __forceinline__ void mma_bf16(float* c, const uint32_t* a, const uint32_t* b) {
    asm volatile("mma.sync.aligned.m16n8k16.row.col.f32.bf16.bf16.f32 "
        "{%0,%1,%2,%3}, {%4,%5,%6,%7}, {%8,%9}, {%0,%1,%2,%3};"
        : "+f"(c[0]), "+f"(c[1]), "+f"(c[2]), "+f"(c[3])
        : "r"(a[0]), "r"(a[1]), "r"(a[2]), "r"(a[3]), "r"(b[0]), "r"(b[1]));
}
#define CP16(dst, src) \
    asm volatile("cp.async.cg.shared.global [%0], [%1], 16;" :: "r"(dst), "l"(src))
#define CP_COMMIT() asm volatile("cp.async.commit_group;" ::: "memory")
#define CP_WAIT0()  asm volatile("cp.async.wait_group 0;" ::: "memory")
#define CP_WAIT1()  asm volatile("cp.async.wait_group 1;" ::: "memory")

__device__ __forceinline__ void split2(float f0, float f1, uint32_t& hi, uint32_t& lo) {
    __nv_bfloat16 h0 = __float2bfloat16(f0);
    __nv_bfloat16 h1 = __float2bfloat16(f1);
    __nv_bfloat16 l0 = __float2bfloat16(f0 - __bfloat162float(h0));
    __nv_bfloat16 l1 = __float2bfloat16(f1 - __bfloat162float(h1));
    hi = (uint32_t)__bfloat16_as_ushort(h0) | ((uint32_t)__bfloat16_as_ushort(h1) << 16);
    lo = (uint32_t)__bfloat16_as_ushort(l0) | ((uint32_t)__bfloat16_as_ushort(l1) << 16);
}

// ---------------- global scratch ----------------
__device__ __nv_bfloat16 g_WxT_hi[HH * DD];     // [n][k] = hi(Wx[k][n])
__device__ __nv_bfloat16 g_WxT_lo[HH * DD];
__device__ __nv_bfloat16 g_WhT_hi[HH * HH];     // [n][k] = hi(Wh[k][n])
__device__ __nv_bfloat16 g_WhT_lo[HH * HH];
__device__ __nv_bfloat16 g_h_hi[2][NB * HH];    // ping-pong split hidden state
__device__ __nv_bfloat16 g_h_lo[2][NB * HH];

__device__ unsigned g_gen   = 0;
__device__ unsigned g_count = 0;

// ---------------- prep ----------------
__global__ void split_transpose_kernel(const float* __restrict__ W, int which) {
    __nv_bfloat16* hi = which ? g_WhT_hi : g_WxT_hi;
    __nv_bfloat16* lo = which ? g_WhT_lo : g_WxT_lo;
    __shared__ float tile[32][33];
    const int kb = blockIdx.x * 32, nb = blockIdx.y * 32;
    const int tx = threadIdx.x, ty = threadIdx.y;    // (32, 8)
#pragma unroll
    for (int i = 0; i < 4; ++i)
        tile[ty + 8 * i][tx] = W[(size_t)(kb + ty + 8 * i) * HH + nb + tx];
    __syncthreads();
#pragma unroll
    for (int i = 0; i < 4; ++i) {
        float f = tile[tx][ty + 8 * i];
        int n = nb + ty + 8 * i, k = kb + tx;
        __nv_bfloat16 h = __float2bfloat16(f);
        hi[(size_t)n * 1024 + k] = h;
        lo[(size_t)n * 1024 + k] = __float2bfloat16(f - __bfloat162float(h));
    }
}

__global__ void split_h0_kernel(const float* __restrict__ h0) {
    int i = blockIdx.x * blockDim.x + threadIdx.x;
    if (i < NB * HH) {
        float f = h0[i];
        __nv_bfloat16 h = __float2bfloat16(f);
        g_h_hi[1][i] = h;                            // step 0 reads parity 1
        g_h_lo[1][i] = __float2bfloat16(f - __bfloat162float(h));
    }
}

// =====================================================================
// Phase 1: out = x @ Wx + b.  CTA 128x128, 256 thr, 8 warps (2m x 4n),
// warp m64 x n32, k-chunks of 64, split-bf16 3-product mma.sync.
// SMEM: AH 16K | AL 16K | BH 16K | BL 16K = 64KB, occupancy 2.
// Coalesced staging: lane -> consecutive 16B of one row.
// =====================================================================
#define P1_SMEM (65536 + 1024)

__global__ __launch_bounds__(256, 2)
void xw_gemm_kernel(const float* __restrict__ x, const float* __restrict__ bias,
                    float* __restrict__ out) {
    extern __shared__ char smem_raw[];
    char* smem = (char*)(((uintptr_t)smem_raw + 1023) & ~(uintptr_t)1023);
    const uint32_t sb = smem_u32(smem);
    const uint32_t AH = sb, AL = sb + 16384, BH = sb + 32768, BL = sb + 49152;

    const int tid = threadIdx.x, lane = tid & 31, w = tid >> 5;
    const int n1 = blockIdx.x * 128, m0 = blockIdx.y * 128;
    const int mq = w & 1, nq = w >> 1;

    const int li = lane >> 3, lr = lane & 7;
    const int aRow = mq * 64 + (li & 1) * 8 + lr;
    const int aKof = (li >> 1) * 16;
    const int bRow = nq * 32 + (li >> 1) * 8 + lr;
    const int bKof = (li & 1) * 16;

    // staging: row group = tid>>3 (32 rows/pass, 4 passes), seg u = tid&7
    const int sr = tid >> 3, su = tid & 7;

    float C[4][4][4];
#pragma unroll
    for (int i = 0; i < 4; ++i)
#pragma unroll
        for (int j = 0; j < 4; ++j)
#pragma unroll
            for (int q = 0; q < 4; ++q) C[i][j][q] = 0.0f;

    for (int c = 0; c < 16; ++c) {
        const int k0 = c * 64;
        // B: cp.async copy of WxT hi/lo (coalesced: 8 lanes cover one 128B row)
#pragma unroll
        for (int p = 0; p < 4; ++p) {
            const int row = p * 32 + sr;
            const uint32_t bo = swz((uint32_t)row * 128 + su * 16);
            CP16(BH + bo, g_WxT_hi + (size_t)(n1 + row) * DD + k0 + su * 8);
            CP16(BL + bo, g_WxT_lo + (size_t)(n1 + row) * DD + k0 + su * 8);
        }
        CP_COMMIT();
        // A: fp32 -> split bf16 (coalesced reads: 8 lanes cover 256B of one row)
#pragma unroll
        for (int p = 0; p < 4; ++p) {
            const int row = p * 32 + sr;
            const float* src = x + (size_t)(m0 + row) * DD + k0 + su * 8;
            float4 f0 = *(const float4*)src;
            float4 f1 = *(const float4*)(src + 4);
            uint32_t hw[4], lw[4];
            split2(f0.x, f0.y, hw[0], lw[0]);
            split2(f0.z, f0.w, hw[1], lw[1]);
            split2(f1.x, f1.y, hw[2], lw[2]);
            split2(f1.z, f1.w, hw[3], lw[3]);
            const uint32_t bo = swz((uint32_t)row * 128 + su * 16);
            *(uint4*)(smem + (AH - sb) + bo) = *(uint4*)hw;
            *(uint4*)(smem + (AL - sb) + bo) = *(uint4*)lw;
        }
        CP_WAIT0();
        __syncthreads();

#pragma unroll
        for (int kk = 0; kk < 64; kk += 16) {
            uint32_t Bh[2][4], Bl[2][4];
#pragma unroll
            for (int g = 0; g < 2; ++g) {
                const uint32_t bo = swz((uint32_t)(bRow + g * 16) * 128 + kk * 2 + bKof);
                ldm_x4(Bh[g], BH + bo);
                ldm_x4(Bl[g], BL + bo);
            }
#pragma unroll
            for (int mt = 0; mt < 4; ++mt) {
                uint32_t Ahf[4], Alf[4];
                const uint32_t ao = swz((uint32_t)(aRow + mt * 16) * 128 + kk * 2 + aKof);
                ldm_x4(Ahf, AH + ao);
                ldm_x4(Alf, AL + ao);
#pragma unroll
                for (int nt = 0; nt < 4; ++nt) {
                    const uint32_t* bh = &Bh[nt >> 1][(nt & 1) * 2];
                    const uint32_t* bl = &Bl[nt >> 1][(nt & 1) * 2];
                    mma_bf16(C[mt][nt], Ahf, bh);
                    mma_bf16(C[mt][nt], Ahf, bl);
                    mma_bf16(C[mt][nt], Alf, bh);
                }
            }
        }
        __syncthreads();
    }

#pragma unroll
    for (int mt = 0; mt < 4; ++mt) {
#pragma unroll
        for (int nt = 0; nt < 4; ++nt) {
            const int r  = m0 + mq * 64 + mt * 16 + (lane >> 2);
            const int cc = n1 + nq * 32 + nt * 8 + (lane & 3) * 2;
            const float b0 = bias[cc], b1 = bias[cc + 1];
            float2 v0 = { C[mt][nt][0] + b0, C[mt][nt][1] + b1 };
            float2 v1 = { C[mt][nt][2] + b0, C[mt][nt][3] + b1 };
            *(float2*)(out + (size_t)r * HH + cc)       = v0;
            *(float2*)(out + (size_t)(r + 8) * HH + cc) = v1;
        }
    }
}

// =====================================================================
// Phase 2: persistent scan. 64 CTAs x 256 thr (8 warps, m16 each),
// CTA N-slice = 16 cols. WhT slice resident (64KB). h streamed via
// double-buffered cp.async (wait_group 1), coalesced staging.
// SMEM: Abuf0 32K | Abuf1 32K | BH 32K | BL 32K = 128KB.
// =====================================================================
#define GRID2 64
#define SC_SMEM (131072 + 1024)

__device__ __forceinline__ void grid_barrier() {
    __syncthreads();
    if (threadIdx.x == 0) {
        __threadfence();
        volatile unsigned* genp = &g_gen;
        unsigned my_gen = *genp;
        unsigned old = atomicAdd(&g_count, 1u);
        if (old == GRID2 - 1) {
            atomicExch(&g_count, 0u);
            __threadfence();
            atomicAdd(&g_gen, 1u);
        } else {
            while (*genp == my_gen) { }
        }
        __threadfence();
    }
    __syncthreads();
}

// coalesced chunk stage: 256 thr, 4 passes of 32 rows; 8 lanes per 128B row
__device__ __forceinline__ void scan_issue_chunk(
        uint32_t dst_h, uint32_t dst_l,
        const __nv_bfloat16* __restrict__ rh, const __nv_bfloat16* __restrict__ rl,
        int c, int tid) {
    const int sr = tid >> 3, su = tid & 7;
#pragma unroll
    for (int p = 0; p < 4; ++p) {
        const int row = p * 32 + sr;
        const uint32_t bo = swz((uint32_t)row * 128 + su * 16);
        CP16(dst_h + bo, rh + (size_t)row * HH + c * 64 + su * 8);
        CP16(dst_l + bo, rl + (size_t)row * HH + c * 64 + su * 8);
    }
}

__global__ __launch_bounds__(256, 1)
void rnn_scan_kernel(float* __restrict__ out) {
    extern __shared__ char smem_raw[];
    char* smem = (char*)(((uintptr_t)smem_raw + 1023) & ~(uintptr_t)1023);
    const uint32_t sb = smem_u32(smem);
    const int tid = threadIdx.x, lane = tid & 31, w = tid >> 5;
    const int n0 = blockIdx.x * 16;

    const uint32_t BH = sb + 65536, BL = sb + 98304;  // 16 chunks x 2KB each

    // stage resident B = WhT[n0..n0+15][:], chunk-blocked, swizzled.
    // 256 thr = 16 rows x 8 segs x 2 (hi/lo)
    {
        const int r = (tid >> 3) & 15, u = tid & 7, isLo = tid >> 7;
        const __nv_bfloat16* src = isLo ? g_WhT_lo : g_WhT_hi;
        char* dst = smem + 65536 + isLo * 32768;
        const uint32_t bo = swz((uint32_t)r * 128 + u * 16);
        for (int c = 0; c < 16; ++c)
            *(uint4*)(dst + c * 2048 + bo) =
                *(const uint4*)(src + (size_t)(n0 + r) * HH + c * 64 + u * 8);
    }
    __syncthreads();

    const int li = lane >> 3, lr = lane & 7;
    const int aRow = w * 16 + (li & 1) * 8 + lr;
    const int aKof = (li >> 1) * 16;
    const int bRow = (li >> 1) * 8 + lr;
    const int bKof = (li & 1) * 16;

    const int r0 = w * 16 + (lane >> 2);              // epilogue rows r0, r0+8
    const int cb = n0 + (lane & 3) * 2;               // + nt*8

    for (int t = 0; t < TT; ++t) {
        const __nv_bfloat16* rh = g_h_hi[(t & 1) ^ 1];
        const __nv_bfloat16* rl = g_h_lo[(t & 1) ^ 1];
        __nv_bfloat16* wh = g_h_hi[t & 1];
        __nv_bfloat16* wl = g_h_lo[t & 1];

        // prefetch xw slice for epilogue
        float2 xp[2][2];
#pragma unroll
        for (int nt = 0; nt < 2; ++nt) {
            const float* p = out + ((size_t)r0 * TT + t) * HH + cb + nt * 8;
            xp[nt][0] = *(const float2*)p;
            xp[nt][1] = *(const float2*)(p + (size_t)8 * TT * HH);
        }

        float C[2][4];
#pragma unroll
        for (int j = 0; j < 2; ++j)
#pragma unroll
            for (int q = 0; q < 4; ++q) C[j][q] = 0.0f;

        for (int c = 0; c < 16; ++c) {
            if (c == 0) {
                scan_issue_chunk(sb, sb + 16384, rh, rl, 0, tid);
                CP_COMMIT();
            }
            if (c < 15) {
                const uint32_t db = sb + ((c + 1) & 1) * 32768;
                scan_issue_chunk(db, db + 16384, rh, rl, c + 1, tid);
                CP_COMMIT();
                CP_WAIT1();          // chunk c done, c+1 still in flight
            } else {
                CP_WAIT0();
            }
            __syncthreads();

            const uint32_t abase_h = sb + (c & 1) * 32768;
            const uint32_t abase_l = abase_h + 16384;
#pragma unroll
            for (int kk = 0; kk < 64; kk += 16) {
                uint32_t Bhf[4], Blf[4];
                const uint32_t bo = (uint32_t)c * 2048 + swz((uint32_t)bRow * 128 + kk * 2 + bKof);
                ldm_x4(Bhf, BH + bo);
                ldm_x4(Blf, BL + bo);
                uint32_t Ahf[4], Alf[4];
                const uint32_t ao = swz((uint32_t)aRow * 128 + kk * 2 + aKof);
                ldm_x4(Ahf, abase_h + ao);
                ldm_x4(Alf, abase_l + ao);
#pragma unroll
                for (int nt = 0; nt < 2; ++nt) {
                    mma_bf16(C[nt], Ahf, &Bhf[nt * 2]);
                    mma_bf16(C[nt], Ahf, &Blf[nt * 2]);
                    mma_bf16(C[nt], Alf, &Bhf[nt * 2]);
                }
            }
            __syncthreads();         // protect buffer reuse by next issue
        }

        // epilogue: h = tanh(xw + acc)
#pragma unroll
        for (int nt = 0; nt < 2; ++nt) {
            const int cc = cb + nt * 8;
            float h00 = tanhf(xp[nt][0].x + C[nt][0]);
            float h01 = tanhf(xp[nt][0].y + C[nt][1]);
            float h10 = tanhf(xp[nt][1].x + C[nt][2]);
            float h11 = tanhf(xp[nt][1].y + C[nt][3]);
            float* p = out + ((size_t)r0 * TT + t) * HH + cc;
            float2 v0 = { h00, h01 }, v1 = { h10, h11 };
            *(float2*)p = v0;
            *(float2*)(p + (size_t)8 * TT * HH) = v1;
            uint32_t hi, lo;
            split2(h00, h01, hi, lo);
            *(uint32_t*)(wh + (size_t)r0 * HH + cc) = hi;
            *(uint32_t*)(wl + (size_t)r0 * HH + cc) = lo;
            split2(h10, h11, hi, lo);
            *(uint32_t*)(wh + (size_t)(r0 + 8) * HH + cc) = hi;
            *(uint32_t*)(wl + (size_t)(r0 + 8) * HH + cc) = lo;
        }

        grid_barrier();   // h_t visible chip-wide (cp.async.cg bypasses L1)
    }
}

// ---------------- launch ----------------
extern "C" void kernel_launch(void* const* d_in, const int* in_sizes, int n_in,
                              void* d_out, int out_size)
{
    const float* x  = (const float*)d_in[0];
    const float* h0 = (const float*)d_in[1];
    const float* Wx = (const float*)d_in[2];
    const float* Wh = (const float*)d_in[3];
    const float* b  = (const float*)d_in[4];
    float* out = (float*)d_out;

    cudaFuncSetAttribute(xw_gemm_kernel,
        cudaFuncAttributeMaxDynamicSharedMemorySize, P1_SMEM);
    cudaFuncSetAttribute(rnn_scan_kernel,
        cudaFuncAttributeMaxDynamicSharedMemorySize, SC_SMEM);

    dim3 tb(32, 8);
    split_transpose_kernel<<<dim3(32, 32), tb>>>(Wx, 0);
    split_transpose_kernel<<<dim3(32, 32), tb>>>(Wh, 1);
    split_h0_kernel<<<(NB * HH + 255) / 256, 256>>>(h0);

    xw_gemm_kernel<<<dim3(8, 512), 256, P1_SMEM>>>(x, b, out);
    rnn_scan_kernel<<<GRID2, 256, SC_SMEM>>>(out);
}

// round 9
// speedup vs baseline: 3.5233x; 1.4751x over previous
#include <cuda_runtime.h>
#include <cuda_bf16.h>
#include <math.h>
#include <stdint.h>

#define NB 128
#define TT 512
#define DD 1024
#define HH 1024

// ---------------- helpers (arch-agnostic PTX only: sm_80+ features) ----------
__device__ __forceinline__ uint32_t smem_u32(const void* p) {
    uint32_t a;
    asm("{ .reg .u64 t; cvta.to.shared.u64 t, %1; cvt.u32.u64 %0, t; }"
        : "=r"(a) : "l"(p));
    return a;
}
__device__ __forceinline__ uint32_t swz(uint32_t b) { return b ^ ((b >> 3) & 0x70); }

__device__ __forceinline__ void ldm_x4(uint32_t* r, uint32_t a) {
    asm volatile("ldmatrix.sync.aligned.m8n8.x4.shared.b16 {%0,%1,%2,%3}, [%4];"
        : "=r"(r[0]), "=r"(r[1]), "=r"(r[2]), "=r"(r[3]) : "r"(a));
}
__device__ __forceinline__ void mma_bf16(float* c, const uint32_t* a, const uint32_t* b) {
    asm volatile("mma.sync.aligned.m16n8k16.row.col.f32.bf16.bf16.f32 "
        "{%0,%1,%2,%3}, {%4,%5,%6,%7}, {%8,%9}, {%0,%1,%2,%3};"
        : "+f"(c[0]), "+f"(c[1]), "+f"(c[2]), "+f"(c[3])
        : "r"(a[0]), "r"(a[1]), "r"(a[2]), "r"(a[3]), "r"(b[0]), "r"(b[1]));
}
#define CP16(dst, src) \
    asm volatile("cp.async.cg.shared.global [%0], [%1], 16;" :: "r"(dst), "l"(src))
#define CP_COMMIT() asm volatile("cp.async.commit_group;" ::: "memory")
#define CP_WAITN(n) asm volatile("cp.async.wait_group %0;" :: "n"(n) : "memory")

__device__ __forceinline__ void split2(float f0, float f1, uint32_t& hi, uint32_t& lo) {
    __nv_bfloat16 h0 = __float2bfloat16(f0);
    __nv_bfloat16 h1 = __float2bfloat16(f1);
    __nv_bfloat16 l0 = __float2bfloat16(f0 - __bfloat162float(h0));
    __nv_bfloat16 l1 = __float2bfloat16(f1 - __bfloat162float(h1));
    hi = (uint32_t)__bfloat16_as_ushort(h0) | ((uint32_t)__bfloat16_as_ushort(h1) << 16);
    lo = (uint32_t)__bfloat16_as_ushort(l0) | ((uint32_t)__bfloat16_as_ushort(l1) << 16);
}

// ---------------- global scratch ----------------
__device__ __nv_bfloat16 g_WxT_hi[HH * DD];     // [n][k] = hi(Wx[k][n])
__device__ __nv_bfloat16 g_WxT_lo[HH * DD];
__device__ __nv_bfloat16 g_WhT_hi[HH * HH];     // [n][k] = hi(Wh[k][n])
__device__ __nv_bfloat16 g_WhT_lo[HH * HH];
__device__ __nv_bfloat16 g_h_hi[2][NB * HH];    // ping-pong split hidden state
__device__ __nv_bfloat16 g_h_lo[2][NB * HH];

__device__ unsigned g_gen   = 0;
__device__ unsigned g_count = 0;

// ---------------- prep ----------------
__global__ void split_transpose_kernel(const float* __restrict__ W, int which) {
    __nv_bfloat16* hi = which ? g_WhT_hi : g_WxT_hi;
    __nv_bfloat16* lo = which ? g_WhT_lo : g_WxT_lo;
    __shared__ float tile[32][33];
    const int kb = blockIdx.x * 32, nb = blockIdx.y * 32;
    const int tx = threadIdx.x, ty = threadIdx.y;    // (32, 8)
#pragma unroll
    for (int i = 0; i < 4; ++i)
        tile[ty + 8 * i][tx] = W[(size_t)(kb + ty + 8 * i) * HH + nb + tx];
    __syncthreads();
#pragma unroll
    for (int i = 0; i < 4; ++i) {
        float f = tile[tx][ty + 8 * i];
        int n = nb + ty + 8 * i, k = kb + tx;
        __nv_bfloat16 h = __float2bfloat16(f);
        hi[(size_t)n * 1024 + k] = h;
        lo[(size_t)n * 1024 + k] = __float2bfloat16(f - __bfloat162float(h));
    }
}

__global__ void split_h0_kernel(const float* __restrict__ h0) {
    int i = blockIdx.x * blockDim.x + threadIdx.x;
    if (i < NB * HH) {
        float f = h0[i];
        __nv_bfloat16 h = __float2bfloat16(f);
        g_h_hi[1][i] = h;                            // step 0 reads parity 1
        g_h_lo[1][i] = __float2bfloat16(f - __bfloat162float(h));
    }
}

// =====================================================================
// Phase 1: out = x @ Wx + b.  (unchanged from R7 — tensor=65%)
// =====================================================================
#define P1_SMEM (65536 + 1024)

__global__ __launch_bounds__(256, 2)
void xw_gemm_kernel(const float* __restrict__ x, const float* __restrict__ bias,
                    float* __restrict__ out) {
    extern __shared__ char smem_raw[];
    char* smem = (char*)(((uintptr_t)smem_raw + 1023) & ~(uintptr_t)1023);
    const uint32_t sb = smem_u32(smem);
    const uint32_t AH = sb, AL = sb + 16384, BH = sb + 32768, BL = sb + 49152;

    const int tid = threadIdx.x, lane = tid & 31, w = tid >> 5;
    const int n1 = blockIdx.x * 128, m0 = blockIdx.y * 128;
    const int mq = w & 1, nq = w >> 1;

    const int li = lane >> 3, lr = lane & 7;
    const int aRow = mq * 64 + (li & 1) * 8 + lr;
    const int aKof = (li >> 1) * 16;
    const int bRow = nq * 32 + (li >> 1) * 8 + lr;
    const int bKof = (li & 1) * 16;

    const int sr = tid >> 3, su = tid & 7;

    float C[4][4][4];
#pragma unroll
    for (int i = 0; i < 4; ++i)
#pragma unroll
        for (int j = 0; j < 4; ++j)
#pragma unroll
            for (int q = 0; q < 4; ++q) C[i][j][q] = 0.0f;

    for (int c = 0; c < 16; ++c) {
        const int k0 = c * 64;
#pragma unroll
        for (int p = 0; p < 4; ++p) {
            const int row = p * 32 + sr;
            const uint32_t bo = swz((uint32_t)row * 128 + su * 16);
            CP16(BH + bo, g_WxT_hi + (size_t)(n1 + row) * DD + k0 + su * 8);
            CP16(BL + bo, g_WxT_lo + (size_t)(n1 + row) * DD + k0 + su * 8);
        }
        CP_COMMIT();
#pragma unroll
        for (int p = 0; p < 4; ++p) {
            const int row = p * 32 + sr;
            const float* src = x + (size_t)(m0 + row) * DD + k0 + su * 8;
            float4 f0 = *(const float4*)src;
            float4 f1 = *(const float4*)(src + 4);
            uint32_t hw[4], lw[4];
            split2(f0.x, f0.y, hw[0], lw[0]);
            split2(f0.z, f0.w, hw[1], lw[1]);
            split2(f1.x, f1.y, hw[2], lw[2]);
            split2(f1.z, f1.w, hw[3], lw[3]);
            const uint32_t bo = swz((uint32_t)row * 128 + su * 16);
            *(uint4*)(smem + (AH - sb) + bo) = *(uint4*)hw;
            *(uint4*)(smem + (AL - sb) + bo) = *(uint4*)lw;
        }
        CP_WAITN(0);
        __syncthreads();

#pragma unroll
        for (int kk = 0; kk < 64; kk += 16) {
            uint32_t Bh[2][4], Bl[2][4];
#pragma unroll
            for (int g = 0; g < 2; ++g) {
                const uint32_t bo = swz((uint32_t)(bRow + g * 16) * 128 + kk * 2 + bKof);
                ldm_x4(Bh[g], BH + bo);
                ldm_x4(Bl[g], BL + bo);
            }
#pragma unroll
            for (int mt = 0; mt < 4; ++mt) {
                uint32_t Ahf[4], Alf[4];
                const uint32_t ao = swz((uint32_t)(aRow + mt * 16) * 128 + kk * 2 + aKof);
                ldm_x4(Ahf, AH + ao);
                ldm_x4(Alf, AL + ao);
#pragma unroll
                for (int nt = 0; nt < 4; ++nt) {
                    const uint32_t* bh = &Bh[nt >> 1][(nt & 1) * 2];
                    const uint32_t* bl = &Bl[nt >> 1][(nt & 1) * 2];
                    mma_bf16(C[mt][nt], Ahf, bh);
                    mma_bf16(C[mt][nt], Ahf, bl);
                    mma_bf16(C[mt][nt], Alf, bh);
                }
            }
        }
        __syncthreads();
    }

#pragma unroll
    for (int mt = 0; mt < 4; ++mt) {
#pragma unroll
        for (int nt = 0; nt < 4; ++nt) {
            const int r  = m0 + mq * 64 + mt * 16 + (lane >> 2);
            const int cc = n1 + nq * 32 + nt * 8 + (lane & 3) * 2;
            const float b0 = bias[cc], b1 = bias[cc + 1];
            float2 v0 = { C[mt][nt][0] + b0, C[mt][nt][1] + b1 };
            float2 v1 = { C[mt][nt][2] + b0, C[mt][nt][3] + b1 };
            *(float2*)(out + (size_t)r * HH + cc)       = v0;
            *(float2*)(out + (size_t)(r + 8) * HH + cc) = v1;
        }
    }
}

// =====================================================================
// Phase 2: persistent scan. 128 CTAs = 4 M-splits x 32 N-splits,
// tile 32x32, 128 thr (4 warps m16n16). WhT N-slice resident (128KB).
// h M-slice streamed via 4-stage cp.async pipeline (8KB/stage).
// SMEM: A stages 4x8KB = 32K | BH 64K | BL 64K = 160KB.
// =====================================================================
#define GRID2 128
#define SC_SMEM (32768 + 131072 + 1024)

__device__ __forceinline__ void grid_barrier() {
    __syncthreads();
    if (threadIdx.x == 0) {
        __threadfence();
        volatile unsigned* genp = &g_gen;
        unsigned my_gen = *genp;
        unsigned old = atomicAdd(&g_count, 1u);
        if (old == GRID2 - 1) {
            atomicExch(&g_count, 0u);
            __threadfence();
            atomicAdd(&g_gen, 1u);
        } else {
            while (*genp == my_gen) { }
        }
        __threadfence();
    }
    __syncthreads();
}

// stage one k-chunk (32 rows x 64 k) of the h M-slice: 4 CP16 per thread
__device__ __forceinline__ void scan_issue_chunk(
        uint32_t abase,
        const __nv_bfloat16* __restrict__ rh, const __nv_bfloat16* __restrict__ rl,
        int m0, int c, int tid) {
    const int r2 = tid >> 3, u = tid & 7;
#pragma unroll
    for (int p = 0; p < 2; ++p) {
        const int row = p * 16 + r2;
        const uint32_t bo = swz((uint32_t)row * 128 + u * 16);
        CP16(abase + bo,        rh + (size_t)(m0 + row) * HH + c * 64 + u * 8);
        CP16(abase + 4096 + bo, rl + (size_t)(m0 + row) * HH + c * 64 + u * 8);
    }
}

__global__ __launch_bounds__(128, 1)
void rnn_scan_kernel(float* __restrict__ out) {
    extern __shared__ char smem_raw[];
    char* smem = (char*)(((uintptr_t)smem_raw + 1023) & ~(uintptr_t)1023);
    const uint32_t sb = smem_u32(smem);
    const int tid = threadIdx.x, lane = tid & 31, w = tid >> 5;
    const int bm = blockIdx.x >> 5, bn = blockIdx.x & 31;
    const int m0 = bm * 32, n0 = bn * 32;

    const uint32_t BH = sb + 32768, BL = sb + 98304;  // 16 chunks x 4KB each

    // stage resident B = WhT[n0..n0+31][:], chunk-blocked, swizzled
    {
        const int r2 = tid >> 3, u = tid & 7;
        for (int c = 0; c < 16; ++c) {
#pragma unroll
            for (int p = 0; p < 2; ++p) {
                const int row = p * 16 + r2;
                const uint32_t bo = (uint32_t)c * 4096 + swz((uint32_t)row * 128 + u * 16);
                *(uint4*)(smem + 32768 + bo) =
                    *(const uint4*)(g_WhT_hi + (size_t)(n0 + row) * HH + c * 64 + u * 8);
                *(uint4*)(smem + 98304 + bo) =
                    *(const uint4*)(g_WhT_lo + (size_t)(n0 + row) * HH + c * 64 + u * 8);
            }
        }
    }
    __syncthreads();

    const int mq = w & 1, nq = w >> 1;                // warp m16 x n16 tile
    const int li = lane >> 3, lr = lane & 7;
    const int aRow = mq * 16 + (li & 1) * 8 + lr;
    const int aKof = (li >> 1) * 16;
    const int bRow = nq * 16 + (li >> 1) * 8 + lr;
    const int bKof = (li & 1) * 16;

    const int r0 = m0 + mq * 16 + (lane >> 2);        // epilogue rows r0, r0+8
    const int cb = n0 + nq * 16 + (lane & 3) * 2;     // + nt*8

    for (int t = 0; t < TT; ++t) {
        const __nv_bfloat16* rh = g_h_hi[(t & 1) ^ 1];
        const __nv_bfloat16* rl = g_h_lo[(t & 1) ^ 1];
        __nv_bfloat16* wh = g_h_hi[t & 1];
        __nv_bfloat16* wl = g_h_lo[t & 1];

        // prefetch xw slice for epilogue
        float2 xp[2][2];
#pragma unroll
        for (int nt = 0; nt < 2; ++nt) {
            const float* p = out + ((size_t)r0 * TT + t) * HH + cb + nt * 8;
            xp[nt][0] = *(const float2*)p;
            xp[nt][1] = *(const float2*)(p + (size_t)8 * TT * HH);
        }

        float C[2][4];
#pragma unroll
        for (int j = 0; j < 2; ++j)
#pragma unroll
            for (int q = 0; q < 4; ++q) C[j][q] = 0.0f;

        // prologue: 3 chunks in flight
#pragma unroll
        for (int c = 0; c < 3; ++c) {
            scan_issue_chunk(sb + (uint32_t)c * 8192, rh, rl, m0, c, tid);
            CP_COMMIT();
        }

        for (int c = 0; c < 16; ++c) {
            if (c + 3 < 16) {
                scan_issue_chunk(sb + (uint32_t)((c + 3) & 3) * 8192, rh, rl, m0, c + 3, tid);
                CP_COMMIT();
                CP_WAITN(3);
            } else if (c == 13) { CP_WAITN(2); }
            else if (c == 14)   { CP_WAITN(1); }
            else                { CP_WAITN(0); }
            __syncthreads();

            const uint32_t abase_h = sb + (uint32_t)(c & 3) * 8192;
            const uint32_t abase_l = abase_h + 4096;
#pragma unroll
            for (int kk = 0; kk < 64; kk += 16) {
                uint32_t Bhf[4], Blf[4];
                const uint32_t bo = (uint32_t)c * 4096 + swz((uint32_t)bRow * 128 + kk * 2 + bKof);
                ldm_x4(Bhf, BH + bo);
                ldm_x4(Blf, BL + bo);
                uint32_t Ahf[4], Alf[4];
                const uint32_t ao = swz((uint32_t)aRow * 128 + kk * 2 + aKof);
                ldm_x4(Ahf, abase_h + ao);
                ldm_x4(Alf, abase_l + ao);
#pragma unroll
                for (int nt = 0; nt < 2; ++nt) {
                    mma_bf16(C[nt], Ahf, &Bhf[nt * 2]);
                    mma_bf16(C[nt], Ahf, &Blf[nt * 2]);
                    mma_bf16(C[nt], Alf, &Bhf[nt * 2]);
                }
            }
            __syncthreads();         // protect stage buffer reuse
        }

        // epilogue: h = tanh(xw + acc)
#pragma unroll
        for (int nt = 0; nt < 2; ++nt) {
            const int cc = cb + nt * 8;
            float h00 = tanhf(xp[nt][0].x + C[nt][0]);
            float h01 = tanhf(xp[nt][0].y + C[nt][1]);
            float h10 = tanhf(xp[nt][1].x + C[nt][2]);
            float h11 = tanhf(xp[nt][1].y + C[nt][3]);
            float* p = out + ((size_t)r0 * TT + t) * HH + cc;
            float2 v0 = { h00, h01 }, v1 = { h10, h11 };
            *(float2*)p = v0;
            *(float2*)(p + (size_t)8 * TT * HH) = v1;
            uint32_t hi, lo;
            split2(h00, h01, hi, lo);
            *(uint32_t*)(wh + (size_t)r0 * HH + cc) = hi;
            *(uint32_t*)(wl + (size_t)r0 * HH + cc) = lo;
            split2(h10, h11, hi, lo);
            *(uint32_t*)(wh + (size_t)(r0 + 8) * HH + cc) = hi;
            *(uint32_t*)(wl + (size_t)(r0 + 8) * HH + cc) = lo;
        }

        grid_barrier();   // h_t visible chip-wide (cp.async.cg bypasses L1)
    }
}

// ---------------- launch ----------------
extern "C" void kernel_launch(void* const* d_in, const int* in_sizes, int n_in,
                              void* d_out, int out_size)
{
    const float* x  = (const float*)d_in[0];
    const float* h0 = (const float*)d_in[1];
    const float* Wx = (const float*)d_in[2];
    const float* Wh = (const float*)d_in[3];
    const float* b  = (const float*)d_in[4];
    float* out = (float*)d_out;

    cudaFuncSetAttribute(xw_gemm_kernel,
        cudaFuncAttributeMaxDynamicSharedMemorySize, P1_SMEM);
    cudaFuncSetAttribute(rnn_scan_kernel,
        cudaFuncAttributeMaxDynamicSharedMemorySize, SC_SMEM);

    dim3 tb(32, 8);
    split_transpose_kernel<<<dim3(32, 32), tb>>>(Wx, 0);
    split_transpose_kernel<<<dim3(32, 32), tb>>>(Wh, 1);
    split_h0_kernel<<<(NB * HH + 255) / 256, 256>>>(h0);

    xw_gemm_kernel<<<dim3(8, 512), 256, P1_SMEM>>>(x, b, out);
    rnn_scan_kernel<<<GRID2, 128, SC_SMEM>>>(out);
}

// round 10
// speedup vs baseline: 3.8268x; 1.0862x over previous
#include <cuda_runtime.h>
#include <cuda_bf16.h>
#include <math.h>
#include <stdint.h>

#define NB 128
#define TT 512
#define DD 1024
#define HH 1024

// ---------------- helpers (arch-agnostic PTX only: sm_80+ features) ----------
__device__ __forceinline__ uint32_t smem_u32(const void* p) {
    uint32_t a;
    asm("{ .reg .u64 t; cvta.to.shared.u64 t, %1; cvt.u32.u64 %0, t; }"
        : "=r"(a) : "l"(p));
    return a;
}
__device__ __forceinline__ uint32_t swz(uint32_t b) { return b ^ ((b >> 3) & 0x70); }

__device__ __forceinline__ void ldm_x4(uint32_t* r, uint32_t a) {
    asm volatile("ldmatrix.sync.aligned.m8n8.x4.shared.b16 {%0,%1,%2,%3}, [%4];"
        : "=r"(r[0]), "=r"(r[1]), "=r"(r[2]), "=r"(r[3]) : "r"(a));
}
__device__ __forceinline__ void mma_bf16(float* c, const uint32_t* a, const uint32_t* b) {
    asm volatile("mma.sync.aligned.m16n8k16.row.col.f32.bf16.bf16.f32 "
        "{%0,%1,%2,%3}, {%4,%5,%6,%7}, {%8,%9}, {%0,%1,%2,%3};"
        : "+f"(c[0]), "+f"(c[1]), "+f"(c[2]), "+f"(c[3])
        : "r"(a[0]), "r"(a[1]), "r"(a[2]), "r"(a[3]), "r"(b[0]), "r"(b[1]));
}
#define CP16(dst, src) \
    asm volatile("cp.async.cg.shared.global [%0], [%1], 16;" :: "r"(dst), "l"(src))
#define CP_COMMIT() asm volatile("cp.async.commit_group;" ::: "memory")
#define CP_WAITN(n) asm volatile("cp.async.wait_group %0;" :: "n"(n) : "memory")

__device__ __forceinline__ void split2(float f0, float f1, uint32_t& hi, uint32_t& lo) {
    __nv_bfloat16 h0 = __float2bfloat16(f0);
    __nv_bfloat16 h1 = __float2bfloat16(f1);
    __nv_bfloat16 l0 = __float2bfloat16(f0 - __bfloat162float(h0));
    __nv_bfloat16 l1 = __float2bfloat16(f1 - __bfloat162float(h1));
    hi = (uint32_t)__bfloat16_as_ushort(h0) | ((uint32_t)__bfloat16_as_ushort(h1) << 16);
    lo = (uint32_t)__bfloat16_as_ushort(l0) | ((uint32_t)__bfloat16_as_ushort(l1) << 16);
}

// ---------------- global scratch ----------------
__device__ __nv_bfloat16 g_WxT_hi[HH * DD];     // [n][k] = hi(Wx[k][n])
__device__ __nv_bfloat16 g_WxT_lo[HH * DD];
__device__ __nv_bfloat16 g_WhT_hi[HH * HH];     // [n][k] = hi(Wh[k][n])
__device__ __nv_bfloat16 g_WhT_lo[HH * HH];
__device__ __nv_bfloat16 g_h_hi[2][NB * HH];    // ping-pong split hidden state
__device__ __nv_bfloat16 g_h_lo[2][NB * HH];

// per-bm-group barrier state (padded: 32 unsigned = 128B apart)
__device__ unsigned g_genA[4 * 32];
__device__ unsigned g_cntA[4 * 32];

// ---------------- prep ----------------
__global__ void split_transpose_kernel(const float* __restrict__ W, int which) {
    __nv_bfloat16* hi = which ? g_WhT_hi : g_WxT_hi;
    __nv_bfloat16* lo = which ? g_WhT_lo : g_WxT_lo;
    __shared__ float tile[32][33];
    const int kb = blockIdx.x * 32, nb = blockIdx.y * 32;
    const int tx = threadIdx.x, ty = threadIdx.y;    // (32, 8)
#pragma unroll
    for (int i = 0; i < 4; ++i)
        tile[ty + 8 * i][tx] = W[(size_t)(kb + ty + 8 * i) * HH + nb + tx];
    __syncthreads();
#pragma unroll
    for (int i = 0; i < 4; ++i) {
        float f = tile[tx][ty + 8 * i];
        int n = nb + ty + 8 * i, k = kb + tx;
        __nv_bfloat16 h = __float2bfloat16(f);
        hi[(size_t)n * 1024 + k] = h;
        lo[(size_t)n * 1024 + k] = __float2bfloat16(f - __bfloat162float(h));
    }
}

__global__ void split_h0_kernel(const float* __restrict__ h0) {
    int i = blockIdx.x * blockDim.x + threadIdx.x;
    if (i < NB * HH) {
        float f = h0[i];
        __nv_bfloat16 h = __float2bfloat16(f);
        g_h_hi[1][i] = h;                            // step 0 reads parity 1
        g_h_lo[1][i] = __float2bfloat16(f - __bfloat162float(h));
    }
}

// =====================================================================
// Phase 1: out = x @ Wx + b.  (unchanged — tensor=65%)
// =====================================================================
#define P1_SMEM (65536 + 1024)

__global__ __launch_bounds__(256, 2)
void xw_gemm_kernel(const float* __restrict__ x, const float* __restrict__ bias,
                    float* __restrict__ out) {
    extern __shared__ char smem_raw[];
    char* smem = (char*)(((uintptr_t)smem_raw + 1023) & ~(uintptr_t)1023);
    const uint32_t sb = smem_u32(smem);
    const uint32_t AH = sb, AL = sb + 16384, BH = sb + 32768, BL = sb + 49152;

    const int tid = threadIdx.x, lane = tid & 31, w = tid >> 5;
    const int n1 = blockIdx.x * 128, m0 = blockIdx.y * 128;
    const int mq = w & 1, nq = w >> 1;

    const int li = lane >> 3, lr = lane & 7;
    const int aRow = mq * 64 + (li & 1) * 8 + lr;
    const int aKof = (li >> 1) * 16;
    const int bRow = nq * 32 + (li >> 1) * 8 + lr;
    const int bKof = (li & 1) * 16;

    const int sr = tid >> 3, su = tid & 7;

    float C[4][4][4];
#pragma unroll
    for (int i = 0; i < 4; ++i)
#pragma unroll
        for (int j = 0; j < 4; ++j)
#pragma unroll
            for (int q = 0; q < 4; ++q) C[i][j][q] = 0.0f;

    for (int c = 0; c < 16; ++c) {
        const int k0 = c * 64;
#pragma unroll
        for (int p = 0; p < 4; ++p) {
            const int row = p * 32 + sr;
            const uint32_t bo = swz((uint32_t)row * 128 + su * 16);
            CP16(BH + bo, g_WxT_hi + (size_t)(n1 + row) * DD + k0 + su * 8);
            CP16(BL + bo, g_WxT_lo + (size_t)(n1 + row) * DD + k0 + su * 8);
        }
        CP_COMMIT();
#pragma unroll
        for (int p = 0; p < 4; ++p) {
            const int row = p * 32 + sr;
            const float* src = x + (size_t)(m0 + row) * DD + k0 + su * 8;
            float4 f0 = *(const float4*)src;
            float4 f1 = *(const float4*)(src + 4);
            uint32_t hw[4], lw[4];
            split2(f0.x, f0.y, hw[0], lw[0]);
            split2(f0.z, f0.w, hw[1], lw[1]);
            split2(f1.x, f1.y, hw[2], lw[2]);
            split2(f1.z, f1.w, hw[3], lw[3]);
            const uint32_t bo = swz((uint32_t)row * 128 + su * 16);
            *(uint4*)(smem + (AH - sb) + bo) = *(uint4*)hw;
            *(uint4*)(smem + (AL - sb) + bo) = *(uint4*)lw;
        }
        CP_WAITN(0);
        __syncthreads();

#pragma unroll
        for (int kk = 0; kk < 64; kk += 16) {
            uint32_t Bh[2][4], Bl[2][4];
#pragma unroll
            for (int g = 0; g < 2; ++g) {
                const uint32_t bo = swz((uint32_t)(bRow + g * 16) * 128 + kk * 2 + bKof);
                ldm_x4(Bh[g], BH + bo);
                ldm_x4(Bl[g], BL + bo);
            }
#pragma unroll
            for (int mt = 0; mt < 4; ++mt) {
                uint32_t Ahf[4], Alf[4];
                const uint32_t ao = swz((uint32_t)(aRow + mt * 16) * 128 + kk * 2 + aKof);
                ldm_x4(Ahf, AH + ao);
                ldm_x4(Alf, AL + ao);
#pragma unroll
                for (int nt = 0; nt < 4; ++nt) {
                    const uint32_t* bh = &Bh[nt >> 1][(nt & 1) * 2];
                    const uint32_t* bl = &Bl[nt >> 1][(nt & 1) * 2];
                    mma_bf16(C[mt][nt], Ahf, bh);
                    mma_bf16(C[mt][nt], Ahf, bl);
                    mma_bf16(C[mt][nt], Alf, bh);
                }
            }
        }
        __syncthreads();
    }

#pragma unroll
    for (int mt = 0; mt < 4; ++mt) {
#pragma unroll
        for (int nt = 0; nt < 4; ++nt) {
            const int r  = m0 + mq * 64 + mt * 16 + (lane >> 2);
            const int cc = n1 + nq * 32 + nt * 8 + (lane & 3) * 2;
            const float b0 = bias[cc], b1 = bias[cc + 1];
            float2 v0 = { C[mt][nt][0] + b0, C[mt][nt][1] + b1 };
            float2 v1 = { C[mt][nt][2] + b0, C[mt][nt][3] + b1 };
            *(float2*)(out + (size_t)r * HH + cc)       = v0;
            *(float2*)(out + (size_t)(r + 8) * HH + cc) = v1;
        }
    }
}

// =====================================================================
// Phase 2: persistent scan. 128 CTAs = 4 independent bm-groups x 32
// N-splits, tile 32x32, 128 thr (4 warps m16n16). Per-group 32-arrival
// barrier. K-chunks of 128 (8/step), 4-stage ring, 2-ahead issue,
// ONE sync per chunk. SMEM: A 4x16KB | BH 64K | BL 64K = 192KB.
// =====================================================================
#define GRID2 128
#define SC_SMEM (65536 + 131072 + 1024)

__device__ __forceinline__ void group_barrier(int g) {
    __syncthreads();
    if (threadIdx.x == 0) {
        __threadfence();
        volatile unsigned* genp = &g_genA[g * 32];
        unsigned my_gen = *genp;
        unsigned old = atomicAdd(&g_cntA[g * 32], 1u);
        if (old == 31) {
            atomicExch(&g_cntA[g * 32], 0u);
            __threadfence();
            atomicAdd((unsigned*)&g_genA[g * 32], 1u);
        } else {
            while (*genp == my_gen) { }
        }
        __threadfence();
    }
    __syncthreads();
}

// stage one 128-k chunk (2 sub-chunks of 64k) of the 32-row h M-slice
__device__ __forceinline__ void scan_issue_chunk(
        uint32_t stage,
        const __nv_bfloat16* __restrict__ rh, const __nv_bfloat16* __restrict__ rl,
        int m0, int c, int tid) {
    const int r2 = tid >> 3, u = tid & 7;
#pragma unroll
    for (int s = 0; s < 2; ++s) {
        const int k0 = (2 * c + s) * 64;
        const uint32_t base = stage + (uint32_t)s * 8192;
#pragma unroll
        for (int p = 0; p < 2; ++p) {
            const int row = p * 16 + r2;
            const uint32_t bo = swz((uint32_t)row * 128 + u * 16);
            CP16(base + bo,        rh + (size_t)(m0 + row) * HH + k0 + u * 8);
            CP16(base + 4096 + bo, rl + (size_t)(m0 + row) * HH + k0 + u * 8);
        }
    }
}

__global__ __launch_bounds__(128, 1)
void rnn_scan_kernel(float* __restrict__ out) {
    extern __shared__ char smem_raw[];
    char* smem = (char*)(((uintptr_t)smem_raw + 1023) & ~(uintptr_t)1023);
    const uint32_t sb = smem_u32(smem);
    const int tid = threadIdx.x, lane = tid & 31, w = tid >> 5;
    const int bm = blockIdx.x >> 5, bn = blockIdx.x & 31;
    const int m0 = bm * 32, n0 = bn * 32;

    const uint32_t BH = sb + 65536, BL = sb + 131072;  // 16 x 4KB (64k) blocks

    // stage resident B = WhT[n0..n0+31][:], 64k-block layout, swizzled
    {
        const int r2 = tid >> 3, u = tid & 7;
        for (int c = 0; c < 16; ++c) {
#pragma unroll
            for (int p = 0; p < 2; ++p) {
                const int row = p * 16 + r2;
                const uint32_t bo = (uint32_t)c * 4096 + swz((uint32_t)row * 128 + u * 16);
                *(uint4*)(smem + 65536 + bo) =
                    *(const uint4*)(g_WhT_hi + (size_t)(n0 + row) * HH + c * 64 + u * 8);
                *(uint4*)(smem + 131072 + bo) =
                    *(const uint4*)(g_WhT_lo + (size_t)(n0 + row) * HH + c * 64 + u * 8);
            }
        }
    }
    __syncthreads();

    const int mq = w & 1, nq = w >> 1;                // warp m16 x n16 tile
    const int li = lane >> 3, lr = lane & 7;
    const int aRow = mq * 16 + (li & 1) * 8 + lr;
    const int aKof = (li >> 1) * 16;
    const int bRow = nq * 16 + (li >> 1) * 8 + lr;
    const int bKof = (li & 1) * 16;

    const int r0 = m0 + mq * 16 + (lane >> 2);        // epilogue rows r0, r0+8
    const int cb = n0 + nq * 16 + (lane & 3) * 2;     // + nt*8

    for (int t = 0; t < TT; ++t) {
        const __nv_bfloat16* rh = g_h_hi[(t & 1) ^ 1];
        const __nv_bfloat16* rl = g_h_lo[(t & 1) ^ 1];
        __nv_bfloat16* wh = g_h_hi[t & 1];
        __nv_bfloat16* wl = g_h_lo[t & 1];

        // prologue: 2 chunks in flight
        scan_issue_chunk(sb,         rh, rl, m0, 0, tid); CP_COMMIT();
        scan_issue_chunk(sb + 16384, rh, rl, m0, 1, tid); CP_COMMIT();

        // prefetch xw slice for epilogue (overlaps with cp.async)
        float2 xp[2][2];
#pragma unroll
        for (int nt = 0; nt < 2; ++nt) {
            const float* p = out + ((size_t)r0 * TT + t) * HH + cb + nt * 8;
            xp[nt][0] = *(const float2*)p;
            xp[nt][1] = *(const float2*)(p + (size_t)8 * TT * HH);
        }

        float C[2][4];
#pragma unroll
        for (int j = 0; j < 2; ++j)
#pragma unroll
            for (int q = 0; q < 4; ++q) C[j][q] = 0.0f;

        for (int c = 0; c < 8; ++c) {
            if (c + 2 < 8) {
                scan_issue_chunk(sb + (uint32_t)((c + 2) & 3) * 16384, rh, rl, m0, c + 2, tid);
                CP_COMMIT();
                CP_WAITN(2);         // chunk c landed; c+1, c+2 in flight
            } else if (c == 6) { CP_WAITN(1); }
            else               { CP_WAITN(0); }
            __syncthreads();         // single sync: ring(4) + 2-ahead => safe

            const uint32_t stage = sb + (uint32_t)(c & 3) * 16384;
#pragma unroll
            for (int s = 0; s < 2; ++s) {
                const uint32_t abase_h = stage + (uint32_t)s * 8192;
                const uint32_t abase_l = abase_h + 4096;
                const uint32_t bblk = (uint32_t)(2 * c + s) * 4096;
#pragma unroll
                for (int kk = 0; kk < 64; kk += 16) {
                    uint32_t Bhf[4], Blf[4];
                    const uint32_t bo = bblk + swz((uint32_t)bRow * 128 + kk * 2 + bKof);
                    ldm_x4(Bhf, BH + bo);
                    ldm_x4(Blf, BL + bo);
                    uint32_t Ahf[4], Alf[4];
                    const uint32_t ao = swz((uint32_t)aRow * 128 + kk * 2 + aKof);
                    ldm_x4(Ahf, abase_h + ao);
                    ldm_x4(Alf, abase_l + ao);
#pragma unroll
                    for (int nt = 0; nt < 2; ++nt) {
                        mma_bf16(C[nt], Ahf, &Bhf[nt * 2]);
                        mma_bf16(C[nt], Ahf, &Blf[nt * 2]);
                        mma_bf16(C[nt], Alf, &Bhf[nt * 2]);
                    }
                }
            }
        }

        // epilogue: h = tanh(xw + acc)
#pragma unroll
        for (int nt = 0; nt < 2; ++nt) {
            const int cc = cb + nt * 8;
            float h00 = tanhf(xp[nt][0].x + C[nt][0]);
            float h01 = tanhf(xp[nt][0].y + C[nt][1]);
            float h10 = tanhf(xp[nt][1].x + C[nt][2]);
            float h11 = tanhf(xp[nt][1].y + C[nt][3]);
            float* p = out + ((size_t)r0 * TT + t) * HH + cc;
            float2 v0 = { h00, h01 }, v1 = { h10, h11 };
            *(float2*)p = v0;
            *(float2*)(p + (size_t)8 * TT * HH) = v1;
            uint32_t hi, lo;
            split2(h00, h01, hi, lo);
            *(uint32_t*)(wh + (size_t)r0 * HH + cc) = hi;
            *(uint32_t*)(wl + (size_t)r0 * HH + cc) = lo;
            split2(h10, h11, hi, lo);
            *(uint32_t*)(wh + (size_t)(r0 + 8) * HH + cc) = hi;
            *(uint32_t*)(wl + (size_t)(r0 + 8) * HH + cc) = lo;
        }

        group_barrier(bm);   // only the 32 CTAs sharing this bm must sync
    }
}

// ---------------- launch ----------------
extern "C" void kernel_launch(void* const* d_in, const int* in_sizes, int n_in,
                              void* d_out, int out_size)
{
    const float* x  = (const float*)d_in[0];
    const float* h0 = (const float*)d_in[1];
    const float* Wx = (const float*)d_in[2];
    const float* Wh = (const float*)d_in[3];
    const float* b  = (const float*)d_in[4];
    float* out = (float*)d_out;

    cudaFuncSetAttribute(xw_gemm_kernel,
        cudaFuncAttributeMaxDynamicSharedMemorySize, P1_SMEM);
    cudaFuncSetAttribute(rnn_scan_kernel,
        cudaFuncAttributeMaxDynamicSharedMemorySize, SC_SMEM);

    dim3 tb(32, 8);
    split_transpose_kernel<<<dim3(32, 32), tb>>>(Wx, 0);
    split_transpose_kernel<<<dim3(32, 32), tb>>>(Wh, 1);
    split_h0_kernel<<<(NB * HH + 255) / 256, 256>>>(h0);

    xw_gemm_kernel<<<dim3(8, 512), 256, P1_SMEM>>>(x, b, out);
    rnn_scan_kernel<<<GRID2, 128, SC_SMEM>>>(out);
}